// round 6
// baseline (speedup 1.0000x reference)
#include <cuda_runtime.h>
#include <cstdint>

// ============================================================================
// PillarFeatureNet (exact algebraic restructuring):
// pass1: raw/per-voxel moments, prefetched grid-stride; last block finalizes
//        BN params (fused) and self-resets state for graph replay.
// pass2: folded 4->64 linear; per-voxel offset commutes out of the max;
//        4-points-per-iter via LDS.128 + packed f32x2 FMA; NaN tail padding;
//        prefetch of next voxel's points.
// ============================================================================

#define MAX_N 60000
#define BLOCK 256
#define GRID  592
#define NWARP (BLOCK / 32)
#define NSTAT 54

// stats layout:
// [0..13]  G1_i (4), G2_ij (10: 00,01,02,03,11,12,13,22,23,33)
// [14..25] U_ij = sum m_i sv_j (i:0..2, j:0..3) at 14+4i+j
// [26..29] Qx_j = sum px sv_j      [30..33] Qy_j = sum py sv_j
// [34..39] V_ij = sum sa_i m_j (sym 3x3)   [40..42] Wx_i  [43..45] Wy_i
// [46..48] Ksa_i  [49..51] Rxx,Rxy,Ryy  [52..53] Lx,Ly
__device__ float    g_stats[NSTAT];       // zero at load; last block re-zeroes
__device__ unsigned g_count;              // zero at load; last block resets
__device__ float    g_params[10 * 64];    // rows: A0..A3, B0..B4, T
__device__ float4   g_meta[MAX_N];        // (m0, m1, m2, k)

__constant__ unsigned char c_iA[32] = {3,3,3,4,4,5, 3,4,5, 3,4,5, 3,4,5, 8,8,9, 8,9,
                                       10,10,10,10,10,10,10,10,10,10,10,10};
__constant__ unsigned char c_iB[32] = {0,1,2,1,2,2, 6,6,6, 7,7,7, 10,10,10, 6,7,7, 10,10,
                                       10,10,10,10,10,10,10,10,10,10,10,10};

__device__ __forceinline__ float wsum(float x) {
#pragma unroll
    for (int o = 16; o; o >>= 1) x += __shfl_xor_sync(0xffffffffu, x, o);
    return x;
}

#define FMA2(d, a, b, c) asm("fma.rn.f32x2 %0, %1, %2, %3;" : "=l"(d) : "l"(a), "l"(b), "l"(c))
#define MUL2(d, a, b)    asm("mul.rn.f32x2 %0, %1, %2;"     : "=l"(d) : "l"(a), "l"(b))
#define PACK2(d, lo, hi) asm("mov.b64 %0, {%1, %2};" : "=l"(d) : "f"(lo), "f"(hi))
#define UNPACK2(lo, hi, s) asm("mov.b64 {%0, %1}, %2;" : "=f"(lo), "=f"(hi) : "l"(s))

// ---------------------------------------------------------------------------
// Pass 1 + fused finalize (prefetched)
// ---------------------------------------------------------------------------
__global__ void __launch_bounds__(BLOCK) k_pass1(
    const float4* __restrict__ vox, const int* __restrict__ npts,
    const int4* __restrict__ coors, const float* __restrict__ Wm,
    const float* __restrict__ gm, const float* __restrict__ bt,
    float invNP, int N)
{
    const int lane = threadIdx.x & 31;
    const int wid  = threadIdx.x >> 5;
    const int warp = blockIdx.x * NWARP + wid;
    const int nwarps = GRID * NWARP;

    __shared__ float q_sm[NWARP][12];
    __shared__ float red[NWARP][NSTAT];

    float a[14];
#pragma unroll
    for (int i = 0; i < 14; i++) a[i] = 0.0f;
    float UQ[20];
#pragma unroll
    for (int i = 0; i < 20; i++) UQ[i] = 0.0f;
    float pv = 0.0f;
    const int ia = c_iA[lane], ib = c_iB[lane];

    float4 pre_v = make_float4(0.f, 0.f, 0.f, 0.f);
    int    pre_k = 0;
    int n = warp;
    if (n < N) { pre_k = __ldg(&npts[n]); pre_v = vox[(size_t)n * 32 + lane]; }

    for (; n < N; n += nwarps) {
        const int k = pre_k;
        const float4 v = pre_v;
        const int n2 = n + nwarps;
        if (n2 < N) { pre_k = __ldg(&npts[n2]); pre_v = vox[(size_t)n2 * 32 + lane]; }

        if (k == 0) {
            if (lane == 0) g_meta[n] = make_float4(0.0f, 0.0f, 0.0f, 0.0f);
            continue;
        }
        float4 u = v;
        if (lane >= k) { u.x = 0.f; u.y = 0.f; u.z = 0.f; u.w = 0.f; }

        a[0]  += u.x;        a[1]  += u.y;        a[2]  += u.z;        a[3]  += u.w;
        a[4]  += u.x * u.x;  a[5]  += u.x * u.y;  a[6]  += u.x * u.z;  a[7]  += u.x * u.w;
        a[8]  += u.y * u.y;  a[9]  += u.y * u.z;  a[10] += u.y * u.w;
        a[11] += u.z * u.z;  a[12] += u.z * u.w;  a[13] += u.w * u.w;

        const float sa0 = wsum(v.x), sa1 = wsum(v.y), sa2 = wsum(v.z);
        const float kf = (float)k, inv = 1.0f / kf;
        const float m0 = sa0 * inv, m1 = sa1 * inv, m2 = sa2 * inv;
        const int4 cc = coors[n];
        const float px = (float)cc.y * 0.1f + (0.05f - 20.0f);
        const float py = (float)cc.z * 0.1f + (0.05f - 20.0f);

        UQ[0]  += m0 * u.x;  UQ[1]  += m0 * u.y;  UQ[2]  += m0 * u.z;  UQ[3]  += m0 * u.w;
        UQ[4]  += m1 * u.x;  UQ[5]  += m1 * u.y;  UQ[6]  += m1 * u.z;  UQ[7]  += m1 * u.w;
        UQ[8]  += m2 * u.x;  UQ[9]  += m2 * u.y;  UQ[10] += m2 * u.z;  UQ[11] += m2 * u.w;
        UQ[12] += px * u.x;  UQ[13] += px * u.y;  UQ[14] += px * u.z;  UQ[15] += px * u.w;
        UQ[16] += py * u.x;  UQ[17] += py * u.y;  UQ[18] += py * u.z;  UQ[19] += py * u.w;

        if (lane == 0) {
            float4* qs = (float4*)q_sm[wid];
            qs[0] = make_float4(m0, m1, m2, sa0);
            qs[1] = make_float4(sa1, sa2, px, py);
            qs[2] = make_float4(kf * px, kf * py, 1.0f, 0.0f);
            g_meta[n] = make_float4(m0, m1, m2, kf);
        }
        __syncwarp();
        pv = fmaf(q_sm[wid][ia], q_sm[wid][ib], pv);
        __syncwarp();
    }

#pragma unroll
    for (int i = 0; i < 14; i++) a[i] = wsum(a[i]);
#pragma unroll
    for (int i = 0; i < 20; i++) UQ[i] = wsum(UQ[i]);
    if (lane == 0) {
#pragma unroll
        for (int i = 0; i < 14; i++) red[wid][i] = a[i];
#pragma unroll
        for (int i = 0; i < 20; i++) red[wid][14 + i] = UQ[i];
    }
    if (lane < 20) red[wid][34 + lane] = pv;
    __syncthreads();
    if (threadIdx.x < NSTAT) {
        float s = 0.0f;
#pragma unroll
        for (int w = 0; w < NWARP; w++) s += red[w][threadIdx.x];
        atomicAdd(&g_stats[threadIdx.x], s);
    }
    __threadfence();
    __shared__ unsigned s_last;
    if (threadIdx.x == 0) s_last = atomicAdd(&g_count, 1u);
    __syncthreads();
    if (s_last != GRID - 1) return;
    __threadfence();

    // ---------------- finalize (last block only) ----------------
    __shared__ float S[9];
    __shared__ float M[9][9];
    if (threadIdx.x == 0) {
        float st[NSTAT];
#pragma unroll
        for (int i = 0; i < NSTAT; i++) st[i] = __ldcg(&g_stats[i]);

        auto G2 = [&](int i, int j) -> float {
            if (i > j) { int t = i; i = j; j = t; }
            const int base[4] = {0, 4, 7, 9};
            return st[4 + base[i] + (j - i)];
        };
        auto U = [&](int i, int j) -> float { return st[14 + i * 4 + j]; };
        auto V = [&](int i, int j) -> float {
            int lo = i < j ? i : j, hi = i < j ? j : i;
            const int b3[3] = {0, 3, 5};
            return st[34 + b3[lo] + (hi - lo)];
        };
        const float* Qx = st + 26; const float* Qy = st + 30;
        const float* Wx = st + 40; const float* Wy = st + 43; const float* Ksa = st + 46;
        const float Rxx = st[49], Rxy = st[50], Ryy = st[51], Lx = st[52], Ly = st[53];

        S[0] = st[0]; S[1] = st[1]; S[2] = st[2]; S[3] = st[3];
        S[4] = st[0] - Ksa[0]; S[5] = st[1] - Ksa[1]; S[6] = st[2] - Ksa[2];
        S[7] = st[0] - Lx;     S[8] = st[1] - Ly;

        for (int i = 0; i < 4; i++)
            for (int j = 0; j < 4; j++) M[i][j] = G2(i, j);
        for (int j = 0; j < 3; j++)
            for (int i = 0; i < 4; i++) {
                const float m = G2(i, j) - U(j, i);
                M[i][4 + j] = m; M[4 + j][i] = m;
            }
        for (int i = 0; i < 3; i++)
            for (int j = 0; j < 3; j++)
                M[4 + i][4 + j] = G2(i, j) - U(i, j) - U(j, i) + V(i, j);
        for (int i = 0; i < 4; i++) {
            float m = G2(i, 0) - Qx[i]; M[i][7] = m; M[7][i] = m;
            m       = G2(i, 1) - Qy[i]; M[i][8] = m; M[8][i] = m;
        }
        for (int i = 0; i < 3; i++) {
            float m = G2(i, 0) - Qx[i] - U(i, 0) + Wx[i]; M[4 + i][7] = m; M[7][4 + i] = m;
            m       = G2(i, 1) - Qy[i] - U(i, 1) + Wy[i]; M[4 + i][8] = m; M[8][4 + i] = m;
        }
        M[7][7] = G2(0, 0) - 2.0f * Qx[0] + Rxx;
        M[7][8] = G2(0, 1) - Qx[1] - Qy[0] + Rxy; M[8][7] = M[7][8];
        M[8][8] = G2(1, 1) - 2.0f * Qy[1] + Ryy;
    }
    __syncthreads();

    if (threadIdx.x < NSTAT) g_stats[threadIdx.x] = 0.0f;
    if (threadIdx.x == 0)    g_count = 0u;

    const int o = threadIdx.x;
    if (o < 64) {
        float w[9];
#pragma unroll
        for (int j = 0; j < 9; j++) w[j] = Wm[o * 9 + j];
        float mean = 0.0f;
#pragma unroll
        for (int j = 0; j < 9; j++) mean += w[j] * S[j];
        mean *= invNP;
        float e2 = 0.0f;
#pragma unroll
        for (int i = 0; i < 9; i++) {
            float acc = 0.0f;
#pragma unroll
            for (int j = 0; j < 9; j++) acc += w[j] * M[i][j];
            e2 += w[i] * acc;
        }
        e2 *= invNP;
        const float var = e2 - mean * mean;
        const float sc  = gm[o] * rsqrtf(var + 1e-3f);
        const float sh  = bt[o] - mean * sc;

        g_params[0 * 64 + o] = sc * (w[0] + w[4] + w[7]);
        g_params[1 * 64 + o] = sc * (w[1] + w[5] + w[8]);
        g_params[2 * 64 + o] = sc * (w[2] + w[6]);
        g_params[3 * 64 + o] = sc * w[3];
        g_params[4 * 64 + o] = sc * w[4];
        g_params[5 * 64 + o] = sc * w[5];
        g_params[6 * 64 + o] = sc * w[6];
        g_params[7 * 64 + o] = sc * w[7];
        g_params[8 * 64 + o] = sc * w[8];
        g_params[9 * 64 + o] = sh;
    }
}

// ---------------------------------------------------------------------------
// Pass 2: warp/voxel; lane = channels (2l, 2l+1); 4 points per iter via
// LDS.128 halves -> f32x2 FMA chains; NaN tail padding; off applied post-max.
// ---------------------------------------------------------------------------
__global__ void __launch_bounds__(BLOCK, 4) k_pass2(
    const float4* __restrict__ vox, const int4* __restrict__ coors,
    float2* __restrict__ out, int N)
{
    const int lane = threadIdx.x & 31;
    const int wid  = threadIdx.x >> 5;
    const int warp = blockIdx.x * NWARP + wid;
    const int nwarps = GRID * NWARP;
    const int c = lane * 2;

    const float A0a = g_params[0 * 64 + c], A0b = g_params[0 * 64 + c + 1];
    const float A1a = g_params[1 * 64 + c], A1b = g_params[1 * 64 + c + 1];
    const float A2a = g_params[2 * 64 + c], A2b = g_params[2 * 64 + c + 1];
    const float A3a = g_params[3 * 64 + c], A3b = g_params[3 * 64 + c + 1];
    const float B0a = g_params[4 * 64 + c], B0b = g_params[4 * 64 + c + 1];
    const float B1a = g_params[5 * 64 + c], B1b = g_params[5 * 64 + c + 1];
    const float B2a = g_params[6 * 64 + c], B2b = g_params[6 * 64 + c + 1];
    const float B3a = g_params[7 * 64 + c], B3b = g_params[7 * 64 + c + 1];
    const float B4a = g_params[8 * 64 + c], B4b = g_params[8 * 64 + c + 1];
    const float Ta  = g_params[9 * 64 + c], Tb  = g_params[9 * 64 + c + 1];

    uint64_t A0pa, A1pa, A2pa, A3pa, A0pb, A1pb, A2pb, A3pb;
    PACK2(A0pa, A0a, A0a); PACK2(A1pa, A1a, A1a); PACK2(A2pa, A2a, A2a); PACK2(A3pa, A3a, A3a);
    PACK2(A0pb, A0b, A0b); PACK2(A1pb, A1b, A1b); PACK2(A2pb, A2b, A2b); PACK2(A3pb, A3b, A3b);

    __shared__ __align__(16) float sx[NWARP][32], sy[NWARP][32], sz[NWARP][32], sw[NWARP][32];
    const float NEG_INF = __int_as_float(0xff800000);
    const float QNAN    = __int_as_float(0x7fffffff);

    float4 pre_v = make_float4(0.f, 0.f, 0.f, 0.f);
    int n = warp;
    if (n < N) pre_v = vox[(size_t)n * 32 + lane];

    for (; n < N; n += nwarps) {
        const float4 v = pre_v;
        const int n2 = n + nwarps;
        if (n2 < N) pre_v = vox[(size_t)n2 * 32 + lane];

        const float4 meta = g_meta[n];
        const int k = (int)meta.w;
        if (k == 0) {
            out[(size_t)n * 32 + lane] = make_float2(0.0f, 0.0f);
            continue;
        }
        // NaN padding for invalid lanes: fmaxf drops NaN operands.
        float4 u = v;
        if (lane >= k) { u.x = QNAN; u.y = QNAN; u.z = QNAN; u.w = QNAN; }
        sx[wid][lane] = u.x; sy[wid][lane] = u.y; sz[wid][lane] = u.z; sw[wid][lane] = u.w;

        const int4 cc = coors[n];
        const float px = (float)cc.y * 0.1f + (0.05f - 20.0f);
        const float py = (float)cc.z * 0.1f + (0.05f - 20.0f);

        float ta = B0a * meta.x;    ta = fmaf(B1a, meta.y, ta);
        ta = fmaf(B2a, meta.z, ta); ta = fmaf(B3a, px, ta); ta = fmaf(B4a, py, ta);
        const float offa = Ta - ta;
        float tb = B0b * meta.x;    tb = fmaf(B1b, meta.y, tb);
        tb = fmaf(B2b, meta.z, tb); tb = fmaf(B3b, px, tb); tb = fmaf(B4b, py, tb);
        const float offb = Tb - tb;

        __syncwarp();
        const ulonglong2* X = (const ulonglong2*)sx[wid];
        const ulonglong2* Y = (const ulonglong2*)sy[wid];
        const ulonglong2* Z = (const ulonglong2*)sz[wid];
        const ulonglong2* W = (const ulonglong2*)sw[wid];

        float ra0 = NEG_INF, ra1 = NEG_INF, rb0 = NEG_INF, rb1 = NEG_INF;
        const int k4 = (k + 3) >> 2;
#pragma unroll 2
        for (int j = 0; j < k4; j++) {
            const ulonglong2 x2 = X[j], y2 = Y[j], z2 = Z[j], w2 = W[j];
            uint64_t t;
            float lo, hi;
            // channel a, points 4j..4j+1
            MUL2(t, w2.x, A3pa); FMA2(t, z2.x, A2pa, t); FMA2(t, y2.x, A1pa, t); FMA2(t, x2.x, A0pa, t);
            UNPACK2(lo, hi, t); ra0 = fmaxf(ra0, lo); ra1 = fmaxf(ra1, hi);
            // channel a, points 4j+2..4j+3
            MUL2(t, w2.y, A3pa); FMA2(t, z2.y, A2pa, t); FMA2(t, y2.y, A1pa, t); FMA2(t, x2.y, A0pa, t);
            UNPACK2(lo, hi, t); ra0 = fmaxf(ra0, lo); ra1 = fmaxf(ra1, hi);
            // channel b, points 4j..4j+1
            MUL2(t, w2.x, A3pb); FMA2(t, z2.x, A2pb, t); FMA2(t, y2.x, A1pb, t); FMA2(t, x2.x, A0pb, t);
            UNPACK2(lo, hi, t); rb0 = fmaxf(rb0, lo); rb1 = fmaxf(rb1, hi);
            // channel b, points 4j+2..4j+3
            MUL2(t, w2.y, A3pb); FMA2(t, z2.y, A2pb, t); FMA2(t, y2.y, A1pb, t); FMA2(t, x2.y, A0pb, t);
            UNPACK2(lo, hi, t); rb0 = fmaxf(rb0, lo); rb1 = fmaxf(rb1, hi);
        }
        const float ra = fmaxf(fmaxf(ra0, ra1) + offa, 0.0f);
        const float rb = fmaxf(fmaxf(rb0, rb1) + offb, 0.0f);
        out[(size_t)n * 32 + lane] = make_float2(ra, rb);
        __syncwarp();
    }
}

// ---------------------------------------------------------------------------
extern "C" void kernel_launch(void* const* d_in, const int* in_sizes, int n_in,
                              void* d_out, int out_size)
{
    const float* voxels = (const float*)d_in[0];
    const int*   npts   = (const int*)d_in[1];
    const int*   coors  = (const int*)d_in[2];
    const float* W      = (const float*)d_in[3];
    const float* gamma  = (const float*)d_in[4];
    const float* beta   = (const float*)d_in[5];
    float*       out    = (float*)d_out;
    const int N = in_sizes[1];

    k_pass1<<<GRID, BLOCK>>>((const float4*)voxels, npts, (const int4*)coors,
                             W, gamma, beta, 1.0f / ((float)N * 32.0f), N);
    k_pass2<<<GRID, BLOCK>>>((const float4*)voxels, (const int4*)coors,
                             (float2*)out, N);
}

// round 7
// speedup vs baseline: 1.1831x; 1.1831x over previous
#include <cuda_runtime.h>
#include <cstdint>

// ============================================================================
// PillarFeatureNet (exact algebraic restructuring):
// pass1: raw/per-voxel moments, prefetched grid-stride, 64-reg cap for
//        4 blocks/SM; last block finalizes BN params + self-resets state.
// pass2: folded 4->64 linear; B/T coefficients in smem (reg relief -> 5
//        blocks/SM); packed f32x2 over point pairs; NaN tail padding;
//        per-voxel offset applied after the max.
// ============================================================================

#define MAX_N 60000
#define BLOCK 256
#define GRID  592
#define NWARP (BLOCK / 32)
#define NSTAT 54

// stats layout:
// [0..13]  G1_i (4), G2_ij (10: 00,01,02,03,11,12,13,22,23,33)
// [14..25] U_ij = sum m_i sv_j (i:0..2, j:0..3) at 14+4i+j
// [26..29] Qx_j = sum px sv_j      [30..33] Qy_j = sum py sv_j
// [34..39] V_ij = sum sa_i m_j (sym 3x3)   [40..42] Wx_i  [43..45] Wy_i
// [46..48] Ksa_i  [49..51] Rxx,Rxy,Ryy  [52..53] Lx,Ly
__device__ float    g_stats[NSTAT];       // zero at load; last block re-zeroes
__device__ unsigned g_count;              // zero at load; last block resets
__device__ float    g_params[10 * 64];    // rows: A0..A3, B0..B4, T
__device__ float4   g_meta[MAX_N];        // (m0, m1, m2, k)

__constant__ unsigned char c_iA[32] = {3,3,3,4,4,5, 3,4,5, 3,4,5, 3,4,5, 8,8,9, 8,9,
                                       10,10,10,10,10,10,10,10,10,10,10,10};
__constant__ unsigned char c_iB[32] = {0,1,2,1,2,2, 6,6,6, 7,7,7, 10,10,10, 6,7,7, 10,10,
                                       10,10,10,10,10,10,10,10,10,10,10,10};

__device__ __forceinline__ float wsum(float x) {
#pragma unroll
    for (int o = 16; o; o >>= 1) x += __shfl_xor_sync(0xffffffffu, x, o);
    return x;
}

#define FMA2(d, a, b, c) asm("fma.rn.f32x2 %0, %1, %2, %3;" : "=l"(d) : "l"(a), "l"(b), "l"(c))
#define MUL2(d, a, b)    asm("mul.rn.f32x2 %0, %1, %2;"     : "=l"(d) : "l"(a), "l"(b))
#define PACK2(d, lo, hi) asm("mov.b64 %0, {%1, %2};" : "=l"(d) : "f"(lo), "f"(hi))
#define UNPACK2(lo, hi, s) asm("mov.b64 {%0, %1}, %2;" : "=f"(lo), "=f"(hi) : "l"(s))

// ---------------------------------------------------------------------------
// Pass 1 + fused finalize (prefetched, 64-reg cap -> 4 blocks/SM)
// ---------------------------------------------------------------------------
__global__ void __launch_bounds__(BLOCK, 4) k_pass1(
    const float4* __restrict__ vox, const int* __restrict__ npts,
    const int4* __restrict__ coors, const float* __restrict__ Wm,
    const float* __restrict__ gm, const float* __restrict__ bt,
    float invNP, int N)
{
    const int lane = threadIdx.x & 31;
    const int wid  = threadIdx.x >> 5;
    const int warp = blockIdx.x * NWARP + wid;
    const int nwarps = GRID * NWARP;

    __shared__ float q_sm[NWARP][12];
    __shared__ float red[NWARP][NSTAT];

    float a[14];
#pragma unroll
    for (int i = 0; i < 14; i++) a[i] = 0.0f;
    float UQ[20];
#pragma unroll
    for (int i = 0; i < 20; i++) UQ[i] = 0.0f;
    float pv = 0.0f;
    const int ia = c_iA[lane], ib = c_iB[lane];

    float4 pre_v = make_float4(0.f, 0.f, 0.f, 0.f);
    int    pre_k = 0;
    int n = warp;
    if (n < N) { pre_k = __ldg(&npts[n]); pre_v = vox[(size_t)n * 32 + lane]; }

    for (; n < N; n += nwarps) {
        const int k = pre_k;
        const float4 v = pre_v;
        const int n2 = n + nwarps;
        if (n2 < N) { pre_k = __ldg(&npts[n2]); pre_v = vox[(size_t)n2 * 32 + lane]; }

        if (k == 0) {
            if (lane == 0) g_meta[n] = make_float4(0.0f, 0.0f, 0.0f, 0.0f);
            continue;
        }
        float4 u = v;
        if (lane >= k) { u.x = 0.f; u.y = 0.f; u.z = 0.f; u.w = 0.f; }

        a[0]  += u.x;        a[1]  += u.y;        a[2]  += u.z;        a[3]  += u.w;
        a[4]  += u.x * u.x;  a[5]  += u.x * u.y;  a[6]  += u.x * u.z;  a[7]  += u.x * u.w;
        a[8]  += u.y * u.y;  a[9]  += u.y * u.z;  a[10] += u.y * u.w;
        a[11] += u.z * u.z;  a[12] += u.z * u.w;  a[13] += u.w * u.w;

        const float sa0 = wsum(v.x), sa1 = wsum(v.y), sa2 = wsum(v.z);
        const float kf = (float)k, inv = 1.0f / kf;
        const float m0 = sa0 * inv, m1 = sa1 * inv, m2 = sa2 * inv;
        const int4 cc = coors[n];
        const float px = (float)cc.y * 0.1f + (0.05f - 20.0f);
        const float py = (float)cc.z * 0.1f + (0.05f - 20.0f);

        UQ[0]  += m0 * u.x;  UQ[1]  += m0 * u.y;  UQ[2]  += m0 * u.z;  UQ[3]  += m0 * u.w;
        UQ[4]  += m1 * u.x;  UQ[5]  += m1 * u.y;  UQ[6]  += m1 * u.z;  UQ[7]  += m1 * u.w;
        UQ[8]  += m2 * u.x;  UQ[9]  += m2 * u.y;  UQ[10] += m2 * u.z;  UQ[11] += m2 * u.w;
        UQ[12] += px * u.x;  UQ[13] += px * u.y;  UQ[14] += px * u.z;  UQ[15] += px * u.w;
        UQ[16] += py * u.x;  UQ[17] += py * u.y;  UQ[18] += py * u.z;  UQ[19] += py * u.w;

        if (lane == 0) {
            float4* qs = (float4*)q_sm[wid];
            qs[0] = make_float4(m0, m1, m2, sa0);
            qs[1] = make_float4(sa1, sa2, px, py);
            qs[2] = make_float4(kf * px, kf * py, 1.0f, 0.0f);
            g_meta[n] = make_float4(m0, m1, m2, kf);
        }
        __syncwarp();
        pv = fmaf(q_sm[wid][ia], q_sm[wid][ib], pv);
        __syncwarp();
    }

#pragma unroll
    for (int i = 0; i < 14; i++) a[i] = wsum(a[i]);
#pragma unroll
    for (int i = 0; i < 20; i++) UQ[i] = wsum(UQ[i]);
    if (lane == 0) {
#pragma unroll
        for (int i = 0; i < 14; i++) red[wid][i] = a[i];
#pragma unroll
        for (int i = 0; i < 20; i++) red[wid][14 + i] = UQ[i];
    }
    if (lane < 20) red[wid][34 + lane] = pv;
    __syncthreads();
    if (threadIdx.x < NSTAT) {
        float s = 0.0f;
#pragma unroll
        for (int w = 0; w < NWARP; w++) s += red[w][threadIdx.x];
        atomicAdd(&g_stats[threadIdx.x], s);
    }
    __threadfence();
    __shared__ unsigned s_last;
    if (threadIdx.x == 0) s_last = atomicAdd(&g_count, 1u);
    __syncthreads();
    if (s_last != GRID - 1) return;
    __threadfence();

    // ---------------- finalize (last block only) ----------------
    __shared__ float S[9];
    __shared__ float M[9][9];
    if (threadIdx.x == 0) {
        float st[NSTAT];
#pragma unroll
        for (int i = 0; i < NSTAT; i++) st[i] = __ldcg(&g_stats[i]);

        auto G2 = [&](int i, int j) -> float {
            if (i > j) { int t = i; i = j; j = t; }
            const int base[4] = {0, 4, 7, 9};
            return st[4 + base[i] + (j - i)];
        };
        auto U = [&](int i, int j) -> float { return st[14 + i * 4 + j]; };
        auto V = [&](int i, int j) -> float {
            int lo = i < j ? i : j, hi = i < j ? j : i;
            const int b3[3] = {0, 3, 5};
            return st[34 + b3[lo] + (hi - lo)];
        };
        const float* Qx = st + 26; const float* Qy = st + 30;
        const float* Wx = st + 40; const float* Wy = st + 43; const float* Ksa = st + 46;
        const float Rxx = st[49], Rxy = st[50], Ryy = st[51], Lx = st[52], Ly = st[53];

        S[0] = st[0]; S[1] = st[1]; S[2] = st[2]; S[3] = st[3];
        S[4] = st[0] - Ksa[0]; S[5] = st[1] - Ksa[1]; S[6] = st[2] - Ksa[2];
        S[7] = st[0] - Lx;     S[8] = st[1] - Ly;

        for (int i = 0; i < 4; i++)
            for (int j = 0; j < 4; j++) M[i][j] = G2(i, j);
        for (int j = 0; j < 3; j++)
            for (int i = 0; i < 4; i++) {
                const float m = G2(i, j) - U(j, i);
                M[i][4 + j] = m; M[4 + j][i] = m;
            }
        for (int i = 0; i < 3; i++)
            for (int j = 0; j < 3; j++)
                M[4 + i][4 + j] = G2(i, j) - U(i, j) - U(j, i) + V(i, j);
        for (int i = 0; i < 4; i++) {
            float m = G2(i, 0) - Qx[i]; M[i][7] = m; M[7][i] = m;
            m       = G2(i, 1) - Qy[i]; M[i][8] = m; M[8][i] = m;
        }
        for (int i = 0; i < 3; i++) {
            float m = G2(i, 0) - Qx[i] - U(i, 0) + Wx[i]; M[4 + i][7] = m; M[7][4 + i] = m;
            m       = G2(i, 1) - Qy[i] - U(i, 1) + Wy[i]; M[4 + i][8] = m; M[8][4 + i] = m;
        }
        M[7][7] = G2(0, 0) - 2.0f * Qx[0] + Rxx;
        M[7][8] = G2(0, 1) - Qx[1] - Qy[0] + Rxy; M[8][7] = M[7][8];
        M[8][8] = G2(1, 1) - 2.0f * Qy[1] + Ryy;
    }
    __syncthreads();

    if (threadIdx.x < NSTAT) g_stats[threadIdx.x] = 0.0f;
    if (threadIdx.x == 0)    g_count = 0u;

    const int o = threadIdx.x;
    if (o < 64) {
        float w[9];
#pragma unroll
        for (int j = 0; j < 9; j++) w[j] = Wm[o * 9 + j];
        float mean = 0.0f;
#pragma unroll
        for (int j = 0; j < 9; j++) mean += w[j] * S[j];
        mean *= invNP;
        float e2 = 0.0f;
#pragma unroll
        for (int i = 0; i < 9; i++) {
            float acc = 0.0f;
#pragma unroll
            for (int j = 0; j < 9; j++) acc += w[j] * M[i][j];
            e2 += w[i] * acc;
        }
        e2 *= invNP;
        const float var = e2 - mean * mean;
        const float sc  = gm[o] * rsqrtf(var + 1e-3f);
        const float sh  = bt[o] - mean * sc;

        g_params[0 * 64 + o] = sc * (w[0] + w[4] + w[7]);
        g_params[1 * 64 + o] = sc * (w[1] + w[5] + w[8]);
        g_params[2 * 64 + o] = sc * (w[2] + w[6]);
        g_params[3 * 64 + o] = sc * w[3];
        g_params[4 * 64 + o] = sc * w[4];
        g_params[5 * 64 + o] = sc * w[5];
        g_params[6 * 64 + o] = sc * w[6];
        g_params[7 * 64 + o] = sc * w[7];
        g_params[8 * 64 + o] = sc * w[8];
        g_params[9 * 64 + o] = sh;
    }
}

// ---------------------------------------------------------------------------
// Pass 2: warp/voxel; lane = channels (2l, 2l+1). A coefficients as packed
// splats in regs; B/T coefficients in smem (register relief -> 5 blocks/SM).
// 4 points/iter via LDS.128 + f32x2; NaN tail padding; off post-max.
// ---------------------------------------------------------------------------
__global__ void __launch_bounds__(BLOCK, 5) k_pass2(
    const float4* __restrict__ vox, const int4* __restrict__ coors,
    float2* __restrict__ out, int N)
{
    const int lane = threadIdx.x & 31;
    const int wid  = threadIdx.x >> 5;
    const int warp = blockIdx.x * NWARP + wid;
    const int nwarps = GRID * NWARP;
    const int c = lane * 2;

    // B0..B4, T rows (g_params rows 4..9) staged in smem
    __shared__ float sB[6][64];
    for (int i = threadIdx.x; i < 6 * 64; i += BLOCK)
        (&sB[0][0])[i] = g_params[4 * 64 + i];

    // A rows as packed splats (16 regs)
    uint64_t A0pa, A1pa, A2pa, A3pa, A0pb, A1pb, A2pb, A3pb;
    {
        const float2* P = (const float2*)g_params;   // row r, pair c: P[r*32 + lane]
        float2 t;
        t = P[0 * 32 + lane]; PACK2(A0pa, t.x, t.x); PACK2(A0pb, t.y, t.y);
        t = P[1 * 32 + lane]; PACK2(A1pa, t.x, t.x); PACK2(A1pb, t.y, t.y);
        t = P[2 * 32 + lane]; PACK2(A2pa, t.x, t.x); PACK2(A2pb, t.y, t.y);
        t = P[3 * 32 + lane]; PACK2(A3pa, t.x, t.x); PACK2(A3pb, t.y, t.y);
    }
    __syncthreads();

    __shared__ __align__(16) float sx[NWARP][32], sy[NWARP][32], sz[NWARP][32], sw[NWARP][32];
    const float NEG_INF = __int_as_float(0xff800000);
    const float QNAN    = __int_as_float(0x7fffffff);

    float4 pre_v = make_float4(0.f, 0.f, 0.f, 0.f);
    int n = warp;
    if (n < N) pre_v = vox[(size_t)n * 32 + lane];

    for (; n < N; n += nwarps) {
        const float4 v = pre_v;
        const int n2 = n + nwarps;
        if (n2 < N) pre_v = vox[(size_t)n2 * 32 + lane];

        const float4 meta = g_meta[n];
        const int k = (int)meta.w;
        if (k == 0) {
            out[(size_t)n * 32 + lane] = make_float2(0.0f, 0.0f);
            continue;
        }
        float4 u = v;
        if (lane >= k) { u.x = QNAN; u.y = QNAN; u.z = QNAN; u.w = QNAN; }
        sx[wid][lane] = u.x; sy[wid][lane] = u.y; sz[wid][lane] = u.z; sw[wid][lane] = u.w;

        const int4 cc = coors[n];
        const float px = (float)cc.y * 0.1f + (0.05f - 20.0f);
        const float py = (float)cc.z * 0.1f + (0.05f - 20.0f);

        // off = T - B.(m, px, py) from smem coefficients
        float ta = sB[0][c] * meta.x;
        ta = fmaf(sB[1][c], meta.y, ta); ta = fmaf(sB[2][c], meta.z, ta);
        ta = fmaf(sB[3][c], px, ta);     ta = fmaf(sB[4][c], py, ta);
        const float offa = sB[5][c] - ta;
        float tb = sB[0][c + 1] * meta.x;
        tb = fmaf(sB[1][c + 1], meta.y, tb); tb = fmaf(sB[2][c + 1], meta.z, tb);
        tb = fmaf(sB[3][c + 1], px, tb);     tb = fmaf(sB[4][c + 1], py, tb);
        const float offb = sB[5][c + 1] - tb;

        __syncwarp();
        const ulonglong2* X = (const ulonglong2*)sx[wid];
        const ulonglong2* Y = (const ulonglong2*)sy[wid];
        const ulonglong2* Z = (const ulonglong2*)sz[wid];
        const ulonglong2* W = (const ulonglong2*)sw[wid];

        float ra0 = NEG_INF, ra1 = NEG_INF, rb0 = NEG_INF, rb1 = NEG_INF;
        const int k4 = (k + 3) >> 2;
#pragma unroll 2
        for (int j = 0; j < k4; j++) {
            const ulonglong2 x2 = X[j], y2 = Y[j], z2 = Z[j], w2 = W[j];
            uint64_t t;
            float lo, hi;
            MUL2(t, w2.x, A3pa); FMA2(t, z2.x, A2pa, t); FMA2(t, y2.x, A1pa, t); FMA2(t, x2.x, A0pa, t);
            UNPACK2(lo, hi, t); ra0 = fmaxf(ra0, lo); ra1 = fmaxf(ra1, hi);
            MUL2(t, w2.y, A3pa); FMA2(t, z2.y, A2pa, t); FMA2(t, y2.y, A1pa, t); FMA2(t, x2.y, A0pa, t);
            UNPACK2(lo, hi, t); ra0 = fmaxf(ra0, lo); ra1 = fmaxf(ra1, hi);
            MUL2(t, w2.x, A3pb); FMA2(t, z2.x, A2pb, t); FMA2(t, y2.x, A1pb, t); FMA2(t, x2.x, A0pb, t);
            UNPACK2(lo, hi, t); rb0 = fmaxf(rb0, lo); rb1 = fmaxf(rb1, hi);
            MUL2(t, w2.y, A3pb); FMA2(t, z2.y, A2pb, t); FMA2(t, y2.y, A1pb, t); FMA2(t, x2.y, A0pb, t);
            UNPACK2(lo, hi, t); rb0 = fmaxf(rb0, lo); rb1 = fmaxf(rb1, hi);
        }
        const float ra = fmaxf(fmaxf(ra0, ra1) + offa, 0.0f);
        const float rb = fmaxf(fmaxf(rb0, rb1) + offb, 0.0f);
        out[(size_t)n * 32 + lane] = make_float2(ra, rb);
        __syncwarp();
    }
}

// ---------------------------------------------------------------------------
extern "C" void kernel_launch(void* const* d_in, const int* in_sizes, int n_in,
                              void* d_out, int out_size)
{
    const float* voxels = (const float*)d_in[0];
    const int*   npts   = (const int*)d_in[1];
    const int*   coors  = (const int*)d_in[2];
    const float* W      = (const float*)d_in[3];
    const float* gamma  = (const float*)d_in[4];
    const float* beta   = (const float*)d_in[5];
    float*       out    = (float*)d_out;
    const int N = in_sizes[1];

    k_pass1<<<GRID, BLOCK>>>((const float4*)voxels, npts, (const int4*)coors,
                             W, gamma, beta, 1.0f / ((float)N * 32.0f), N);
    k_pass2<<<GRID, BLOCK>>>((const float4*)voxels, (const int4*)coors,
                             (float2*)out, N);
}

// round 9
// speedup vs baseline: 1.4011x; 1.1843x over previous
#include <cuda_runtime.h>
#include <cstdint>

// ============================================================================
// PillarFeatureNet (exact algebraic restructuring):
// pass1: raw/per-voxel moments (R4-proven config: shfl butterflies, 64-reg
//        cap, 4 blocks/SM); last block finalizes BN params + self-resets.
// pass2: folded 4->64 linear, scalar FFMA chains (minimal regs), A-coeffs in
//        8 regs + B/T in smem, 6 blocks/SM occupancy (GRID = 148*6);
//        per-voxel offset applied post-max; loops only valid points.
// ============================================================================

#define MAX_N 60000
#define BLOCK 256
#define GRID1 592              /* 148 SMs * 4 blocks (pass1, 64-reg cap) */
#define GRID2 888              /* 148 SMs * 6 blocks (pass2, ~40 regs)  */
#define NWARP (BLOCK / 32)
#define NSTAT 54

// stats layout:
// [0..13]  G1_i (4), G2_ij (10: 00,01,02,03,11,12,13,22,23,33)
// [14..25] U_ij = sum m_i sv_j (i:0..2, j:0..3) at 14+4i+j
// [26..29] Qx_j = sum px sv_j      [30..33] Qy_j = sum py sv_j
// [34..39] V_ij = sum sa_i m_j (sym 3x3)   [40..42] Wx_i  [43..45] Wy_i
// [46..48] Ksa_i  [49..51] Rxx,Rxy,Ryy  [52..53] Lx,Ly
__device__ float    g_stats[NSTAT];       // zero at load; last block re-zeroes
__device__ unsigned g_count;              // zero at load; last block resets
__device__ float    g_params[10 * 64];    // rows: A0..A3, B0..B4, T
__device__ float4   g_meta[MAX_N];        // (m0, m1, m2, k)

__constant__ unsigned char c_iA[32] = {3,3,3,4,4,5, 3,4,5, 3,4,5, 3,4,5, 8,8,9, 8,9,
                                       10,10,10,10,10,10,10,10,10,10,10,10};
__constant__ unsigned char c_iB[32] = {0,1,2,1,2,2, 6,6,6, 7,7,7, 10,10,10, 6,7,7, 10,10,
                                       10,10,10,10,10,10,10,10,10,10,10,10};

__device__ __forceinline__ float wsum(float x) {
#pragma unroll
    for (int o = 16; o; o >>= 1) x += __shfl_xor_sync(0xffffffffu, x, o);
    return x;
}

// ---------------------------------------------------------------------------
// Pass 1 + fused finalize (R4-proven: no prefetch, 64-reg cap -> 4 blocks/SM)
// ---------------------------------------------------------------------------
__global__ void __launch_bounds__(BLOCK, 4) k_pass1(
    const float4* __restrict__ vox, const int* __restrict__ npts,
    const int4* __restrict__ coors, const float* __restrict__ Wm,
    const float* __restrict__ gm, const float* __restrict__ bt,
    float invNP, int N)
{
    const int lane = threadIdx.x & 31;
    const int wid  = threadIdx.x >> 5;
    const int warp = blockIdx.x * NWARP + wid;
    const int nwarps = GRID1 * NWARP;

    __shared__ float q_sm[NWARP][12];
    __shared__ float red[NWARP][NSTAT];

    float a[14];
#pragma unroll
    for (int i = 0; i < 14; i++) a[i] = 0.0f;
    float UQ[20];
#pragma unroll
    for (int i = 0; i < 20; i++) UQ[i] = 0.0f;
    float pv = 0.0f;
    const int ia = c_iA[lane], ib = c_iB[lane];

    for (int n = warp; n < N; n += nwarps) {
        const int k = __ldg(&npts[n]);
        if (k == 0) {
            if (lane == 0) g_meta[n] = make_float4(0.0f, 0.0f, 0.0f, 0.0f);
            continue;
        }
        const float4 v = vox[(size_t)n * 32 + lane];
        float4 u = v;
        if (lane >= k) { u.x = 0.f; u.y = 0.f; u.z = 0.f; u.w = 0.f; }

        a[0]  += u.x;        a[1]  += u.y;        a[2]  += u.z;        a[3]  += u.w;
        a[4]  += u.x * u.x;  a[5]  += u.x * u.y;  a[6]  += u.x * u.z;  a[7]  += u.x * u.w;
        a[8]  += u.y * u.y;  a[9]  += u.y * u.z;  a[10] += u.y * u.w;
        a[11] += u.z * u.z;  a[12] += u.z * u.w;  a[13] += u.w * u.w;

        // unmasked all-point xyz sums (reference's points_mean numerator)
        const float sa0 = wsum(v.x), sa1 = wsum(v.y), sa2 = wsum(v.z);
        const float kf = (float)k, inv = 1.0f / kf;
        const float m0 = sa0 * inv, m1 = sa1 * inv, m2 = sa2 * inv;
        const int4 cc = coors[n];
        const float px = (float)cc.y * 0.1f + (0.05f - 20.0f);
        const float py = (float)cc.z * 0.1f + (0.05f - 20.0f);

        UQ[0]  += m0 * u.x;  UQ[1]  += m0 * u.y;  UQ[2]  += m0 * u.z;  UQ[3]  += m0 * u.w;
        UQ[4]  += m1 * u.x;  UQ[5]  += m1 * u.y;  UQ[6]  += m1 * u.z;  UQ[7]  += m1 * u.w;
        UQ[8]  += m2 * u.x;  UQ[9]  += m2 * u.y;  UQ[10] += m2 * u.z;  UQ[11] += m2 * u.w;
        UQ[12] += px * u.x;  UQ[13] += px * u.y;  UQ[14] += px * u.z;  UQ[15] += px * u.w;
        UQ[16] += py * u.x;  UQ[17] += py * u.y;  UQ[18] += py * u.z;  UQ[19] += py * u.w;

        if (lane == 0) {
            float4* qs = (float4*)q_sm[wid];
            qs[0] = make_float4(m0, m1, m2, sa0);
            qs[1] = make_float4(sa1, sa2, px, py);
            qs[2] = make_float4(kf * px, kf * py, 1.0f, 0.0f);
            g_meta[n] = make_float4(m0, m1, m2, kf);
        }
        __syncwarp();
        pv = fmaf(q_sm[wid][ia], q_sm[wid][ib], pv);
        __syncwarp();
    }

#pragma unroll
    for (int i = 0; i < 14; i++) a[i] = wsum(a[i]);
#pragma unroll
    for (int i = 0; i < 20; i++) UQ[i] = wsum(UQ[i]);
    if (lane == 0) {
#pragma unroll
        for (int i = 0; i < 14; i++) red[wid][i] = a[i];
#pragma unroll
        for (int i = 0; i < 20; i++) red[wid][14 + i] = UQ[i];
    }
    if (lane < 20) red[wid][34 + lane] = pv;
    __syncthreads();
    if (threadIdx.x < NSTAT) {
        float s = 0.0f;
#pragma unroll
        for (int w = 0; w < NWARP; w++) s += red[w][threadIdx.x];
        atomicAdd(&g_stats[threadIdx.x], s);
    }
    __threadfence();
    __shared__ unsigned s_last;
    if (threadIdx.x == 0) s_last = atomicAdd(&g_count, 1u);
    __syncthreads();
    if (s_last != GRID1 - 1) return;
    __threadfence();

    // ---------------- finalize (last block only) ----------------
    __shared__ float S[9];
    __shared__ float M[9][9];
    if (threadIdx.x == 0) {
        float st[NSTAT];
#pragma unroll
        for (int i = 0; i < NSTAT; i++) st[i] = __ldcg(&g_stats[i]);

        auto G2 = [&](int i, int j) -> float {
            if (i > j) { int t = i; i = j; j = t; }
            const int base[4] = {0, 4, 7, 9};
            return st[4 + base[i] + (j - i)];
        };
        auto U = [&](int i, int j) -> float { return st[14 + i * 4 + j]; };
        auto V = [&](int i, int j) -> float {
            int lo = i < j ? i : j, hi = i < j ? j : i;
            const int b3[3] = {0, 3, 5};
            return st[34 + b3[lo] + (hi - lo)];
        };
        const float* Qx = st + 26; const float* Qy = st + 30;
        const float* Wx = st + 40; const float* Wy = st + 43; const float* Ksa = st + 46;
        const float Rxx = st[49], Rxy = st[50], Ryy = st[51], Lx = st[52], Ly = st[53];

        S[0] = st[0]; S[1] = st[1]; S[2] = st[2]; S[3] = st[3];
        S[4] = st[0] - Ksa[0]; S[5] = st[1] - Ksa[1]; S[6] = st[2] - Ksa[2];
        S[7] = st[0] - Lx;     S[8] = st[1] - Ly;

        for (int i = 0; i < 4; i++)
            for (int j = 0; j < 4; j++) M[i][j] = G2(i, j);
        for (int j = 0; j < 3; j++)
            for (int i = 0; i < 4; i++) {
                const float m = G2(i, j) - U(j, i);
                M[i][4 + j] = m; M[4 + j][i] = m;
            }
        for (int i = 0; i < 3; i++)
            for (int j = 0; j < 3; j++)
                M[4 + i][4 + j] = G2(i, j) - U(i, j) - U(j, i) + V(i, j);
        for (int i = 0; i < 4; i++) {
            float m = G2(i, 0) - Qx[i]; M[i][7] = m; M[7][i] = m;
            m       = G2(i, 1) - Qy[i]; M[i][8] = m; M[8][i] = m;
        }
        for (int i = 0; i < 3; i++) {
            float m = G2(i, 0) - Qx[i] - U(i, 0) + Wx[i]; M[4 + i][7] = m; M[7][4 + i] = m;
            m       = G2(i, 1) - Qy[i] - U(i, 1) + Wy[i]; M[4 + i][8] = m; M[8][4 + i] = m;
        }
        M[7][7] = G2(0, 0) - 2.0f * Qx[0] + Rxx;
        M[7][8] = G2(0, 1) - Qx[1] - Qy[0] + Rxy; M[8][7] = M[7][8];
        M[8][8] = G2(1, 1) - 2.0f * Qy[1] + Ryy;
    }
    __syncthreads();

    if (threadIdx.x < NSTAT) g_stats[threadIdx.x] = 0.0f;
    if (threadIdx.x == 0)    g_count = 0u;

    const int o = threadIdx.x;
    if (o < 64) {
        float w[9];
#pragma unroll
        for (int j = 0; j < 9; j++) w[j] = Wm[o * 9 + j];
        float mean = 0.0f;
#pragma unroll
        for (int j = 0; j < 9; j++) mean += w[j] * S[j];
        mean *= invNP;
        float e2 = 0.0f;
#pragma unroll
        for (int i = 0; i < 9; i++) {
            float acc = 0.0f;
#pragma unroll
            for (int j = 0; j < 9; j++) acc += w[j] * M[i][j];
            e2 += w[i] * acc;
        }
        e2 *= invNP;
        const float var = e2 - mean * mean;
        const float sc  = gm[o] * rsqrtf(var + 1e-3f);
        const float sh  = bt[o] - mean * sc;

        g_params[0 * 64 + o] = sc * (w[0] + w[4] + w[7]);
        g_params[1 * 64 + o] = sc * (w[1] + w[5] + w[8]);
        g_params[2 * 64 + o] = sc * (w[2] + w[6]);
        g_params[3 * 64 + o] = sc * w[3];
        g_params[4 * 64 + o] = sc * w[4];
        g_params[5 * 64 + o] = sc * w[5];
        g_params[6 * 64 + o] = sc * w[6];
        g_params[7 * 64 + o] = sc * w[7];
        g_params[8 * 64 + o] = sc * w[8];
        g_params[9 * 64 + o] = sh;
    }
}

// ---------------------------------------------------------------------------
// Pass 2: warp/voxel; lane = channels (2l, 2l+1). Scalar FFMA chains;
// A-coeffs in 8 regs, B/T in smem; 6 blocks/SM (GRID2=888) for occupancy;
// off post-max; loops only p<k; dual max accumulators; prefetch next voxel.
// ---------------------------------------------------------------------------
__global__ void __launch_bounds__(BLOCK, 6) k_pass2(
    const float4* __restrict__ vox, const int4* __restrict__ coors,
    float2* __restrict__ out, int N)
{
    const int lane = threadIdx.x & 31;
    const int wid  = threadIdx.x >> 5;
    const int warp = blockIdx.x * NWARP + wid;
    const int nwarps = GRID2 * NWARP;
    const int c = lane * 2;

    // B0..B4, T rows staged in smem (register relief)
    __shared__ float sB[6][64];
    for (int i = threadIdx.x; i < 6 * 64; i += BLOCK)
        (&sB[0][0])[i] = g_params[4 * 64 + i];

    // A rows: 8 scalar regs (channel pair c, c+1 per row)
    const float2* P = (const float2*)g_params;   // row r, pair: P[r*32 + lane]
    const float2 A0 = P[0 * 32 + lane];
    const float2 A1 = P[1 * 32 + lane];
    const float2 A2 = P[2 * 32 + lane];
    const float2 A3 = P[3 * 32 + lane];
    __syncthreads();

    __shared__ __align__(16) float4 pts[NWARP][32];
    const float NEG_INF = __int_as_float(0xff800000);

    float4 pre_v = make_float4(0.f, 0.f, 0.f, 0.f);
    int n = warp;
    if (n < N) pre_v = vox[(size_t)n * 32 + lane];

    for (; n < N; n += nwarps) {
        const float4 v = pre_v;
        const int n2 = n + nwarps;
        if (n2 < N) pre_v = vox[(size_t)n2 * 32 + lane];

        const float4 meta = g_meta[n];
        const int k = (int)meta.w;
        if (k == 0) {
            out[(size_t)n * 32 + lane] = make_float2(0.0f, 0.0f);
            continue;
        }
        pts[wid][lane] = v;

        const int4 cc = coors[n];
        const float px = (float)cc.y * 0.1f + (0.05f - 20.0f);
        const float py = (float)cc.z * 0.1f + (0.05f - 20.0f);

        float ta = sB[0][c] * meta.x;
        ta = fmaf(sB[1][c], meta.y, ta); ta = fmaf(sB[2][c], meta.z, ta);
        ta = fmaf(sB[3][c], px, ta);     ta = fmaf(sB[4][c], py, ta);
        const float offa = sB[5][c] - ta;
        float tb = sB[0][c + 1] * meta.x;
        tb = fmaf(sB[1][c + 1], meta.y, tb); tb = fmaf(sB[2][c + 1], meta.z, tb);
        tb = fmaf(sB[3][c + 1], px, tb);     tb = fmaf(sB[4][c + 1], py, tb);
        const float offb = sB[5][c + 1] - tb;

        __syncwarp();
        float ra0 = NEG_INF, ra1 = NEG_INF, rb0 = NEG_INF, rb1 = NEG_INF;
        const int kp = k & ~1;
#pragma unroll 2
        for (int p = 0; p < kp; p += 2) {
            const float4 u0 = pts[wid][p];
            const float4 u1 = pts[wid][p + 1];
            const float y0a = fmaf(u0.x, A0.x, fmaf(u0.y, A1.x, fmaf(u0.z, A2.x, u0.w * A3.x)));
            const float y0b = fmaf(u0.x, A0.y, fmaf(u0.y, A1.y, fmaf(u0.z, A2.y, u0.w * A3.y)));
            const float y1a = fmaf(u1.x, A0.x, fmaf(u1.y, A1.x, fmaf(u1.z, A2.x, u1.w * A3.x)));
            const float y1b = fmaf(u1.x, A0.y, fmaf(u1.y, A1.y, fmaf(u1.z, A2.y, u1.w * A3.y)));
            ra0 = fmaxf(ra0, y0a); rb0 = fmaxf(rb0, y0b);
            ra1 = fmaxf(ra1, y1a); rb1 = fmaxf(rb1, y1b);
        }
        if (k & 1) {
            const float4 u0 = pts[wid][k - 1];
            ra0 = fmaxf(ra0, fmaf(u0.x, A0.x, fmaf(u0.y, A1.x, fmaf(u0.z, A2.x, u0.w * A3.x))));
            rb0 = fmaxf(rb0, fmaf(u0.x, A0.y, fmaf(u0.y, A1.y, fmaf(u0.z, A2.y, u0.w * A3.y))));
        }
        const float ra = fmaxf(fmaxf(ra0, ra1) + offa, 0.0f);
        const float rb = fmaxf(fmaxf(rb0, rb1) + offb, 0.0f);
        out[(size_t)n * 32 + lane] = make_float2(ra, rb);
        __syncwarp();
    }
}

// ---------------------------------------------------------------------------
extern "C" void kernel_launch(void* const* d_in, const int* in_sizes, int n_in,
                              void* d_out, int out_size)
{
    const float* voxels = (const float*)d_in[0];
    const int*   npts   = (const int*)d_in[1];
    const int*   coors  = (const int*)d_in[2];
    const float* W      = (const float*)d_in[3];
    const float* gamma  = (const float*)d_in[4];
    const float* beta   = (const float*)d_in[5];
    float*       out    = (float*)d_out;
    const int N = in_sizes[1];

    k_pass1<<<GRID1, BLOCK>>>((const float4*)voxels, npts, (const int4*)coors,
                              W, gamma, beta, 1.0f / ((float)N * 32.0f), N);
    k_pass2<<<GRID2, BLOCK>>>((const float4*)voxels, (const int4*)coors,
                              (float2*)out, N);
}

// round 10
// speedup vs baseline: 1.4248x; 1.0169x over previous
#include <cuda_runtime.h>
#include <cstdint>

// ============================================================================
// PillarFeatureNet (exact algebraic restructuring):
// pass1: raw/per-voxel moments (R4-proven config: shfl butterflies, 64-reg
//        cap, 4 blocks/SM); last block finalizes BN params + self-resets.
// pass2: folded 4->64 linear; R4's 2pt-f32x2 SoA inner loop; B/T coeffs in
//        smem; NaN tail padding; offset post-max; 5 blocks/SM (GRID=148*5).
// ============================================================================

#define MAX_N 60000
#define BLOCK 256
#define GRID1 592              /* 148 SMs * 4 blocks (pass1, 64-reg cap) */
#define GRID2 740              /* 148 SMs * 5 blocks (pass2, <=48 regs)  */
#define NWARP (BLOCK / 32)
#define NSTAT 54

// stats layout:
// [0..13]  G1_i (4), G2_ij (10: 00,01,02,03,11,12,13,22,23,33)
// [14..25] U_ij = sum m_i sv_j (i:0..2, j:0..3) at 14+4i+j
// [26..29] Qx_j = sum px sv_j      [30..33] Qy_j = sum py sv_j
// [34..39] V_ij = sum sa_i m_j (sym 3x3)   [40..42] Wx_i  [43..45] Wy_i
// [46..48] Ksa_i  [49..51] Rxx,Rxy,Ryy  [52..53] Lx,Ly
__device__ float    g_stats[NSTAT];       // zero at load; last block re-zeroes
__device__ unsigned g_count;              // zero at load; last block resets
__device__ float    g_params[10 * 64];    // rows: A0..A3, B0..B4, T
__device__ float4   g_meta[MAX_N];        // (m0, m1, m2, k)

__constant__ unsigned char c_iA[32] = {3,3,3,4,4,5, 3,4,5, 3,4,5, 3,4,5, 8,8,9, 8,9,
                                       10,10,10,10,10,10,10,10,10,10,10,10};
__constant__ unsigned char c_iB[32] = {0,1,2,1,2,2, 6,6,6, 7,7,7, 10,10,10, 6,7,7, 10,10,
                                       10,10,10,10,10,10,10,10,10,10,10,10};

__device__ __forceinline__ float wsum(float x) {
#pragma unroll
    for (int o = 16; o; o >>= 1) x += __shfl_xor_sync(0xffffffffu, x, o);
    return x;
}

#define FMA2(d, a, b, c) asm("fma.rn.f32x2 %0, %1, %2, %3;" : "=l"(d) : "l"(a), "l"(b), "l"(c))
#define MUL2(d, a, b)    asm("mul.rn.f32x2 %0, %1, %2;"     : "=l"(d) : "l"(a), "l"(b))
#define PACK2(d, lo, hi) asm("mov.b64 %0, {%1, %2};" : "=l"(d) : "f"(lo), "f"(hi))
#define UNPACK2(lo, hi, s) asm("mov.b64 {%0, %1}, %2;" : "=f"(lo), "=f"(hi) : "l"(s))

// ---------------------------------------------------------------------------
// Pass 1 + fused finalize (R4-proven: no prefetch, 64-reg cap -> 4 blocks/SM)
// ---------------------------------------------------------------------------
__global__ void __launch_bounds__(BLOCK, 4) k_pass1(
    const float4* __restrict__ vox, const int* __restrict__ npts,
    const int4* __restrict__ coors, const float* __restrict__ Wm,
    const float* __restrict__ gm, const float* __restrict__ bt,
    float invNP, int N)
{
    const int lane = threadIdx.x & 31;
    const int wid  = threadIdx.x >> 5;
    const int warp = blockIdx.x * NWARP + wid;
    const int nwarps = GRID1 * NWARP;

    __shared__ float q_sm[NWARP][12];
    __shared__ float red[NWARP][NSTAT];

    float a[14];
#pragma unroll
    for (int i = 0; i < 14; i++) a[i] = 0.0f;
    float UQ[20];
#pragma unroll
    for (int i = 0; i < 20; i++) UQ[i] = 0.0f;
    float pv = 0.0f;
    const int ia = c_iA[lane], ib = c_iB[lane];

    for (int n = warp; n < N; n += nwarps) {
        const int k = __ldg(&npts[n]);
        if (k == 0) {
            if (lane == 0) g_meta[n] = make_float4(0.0f, 0.0f, 0.0f, 0.0f);
            continue;
        }
        const float4 v = vox[(size_t)n * 32 + lane];
        float4 u = v;
        if (lane >= k) { u.x = 0.f; u.y = 0.f; u.z = 0.f; u.w = 0.f; }

        a[0]  += u.x;        a[1]  += u.y;        a[2]  += u.z;        a[3]  += u.w;
        a[4]  += u.x * u.x;  a[5]  += u.x * u.y;  a[6]  += u.x * u.z;  a[7]  += u.x * u.w;
        a[8]  += u.y * u.y;  a[9]  += u.y * u.z;  a[10] += u.y * u.w;
        a[11] += u.z * u.z;  a[12] += u.z * u.w;  a[13] += u.w * u.w;

        // unmasked all-point xyz sums (reference's points_mean numerator)
        const float sa0 = wsum(v.x), sa1 = wsum(v.y), sa2 = wsum(v.z);
        const float kf = (float)k, inv = 1.0f / kf;
        const float m0 = sa0 * inv, m1 = sa1 * inv, m2 = sa2 * inv;
        const int4 cc = coors[n];
        const float px = (float)cc.y * 0.1f + (0.05f - 20.0f);
        const float py = (float)cc.z * 0.1f + (0.05f - 20.0f);

        UQ[0]  += m0 * u.x;  UQ[1]  += m0 * u.y;  UQ[2]  += m0 * u.z;  UQ[3]  += m0 * u.w;
        UQ[4]  += m1 * u.x;  UQ[5]  += m1 * u.y;  UQ[6]  += m1 * u.z;  UQ[7]  += m1 * u.w;
        UQ[8]  += m2 * u.x;  UQ[9]  += m2 * u.y;  UQ[10] += m2 * u.z;  UQ[11] += m2 * u.w;
        UQ[12] += px * u.x;  UQ[13] += px * u.y;  UQ[14] += px * u.z;  UQ[15] += px * u.w;
        UQ[16] += py * u.x;  UQ[17] += py * u.y;  UQ[18] += py * u.z;  UQ[19] += py * u.w;

        if (lane == 0) {
            float4* qs = (float4*)q_sm[wid];
            qs[0] = make_float4(m0, m1, m2, sa0);
            qs[1] = make_float4(sa1, sa2, px, py);
            qs[2] = make_float4(kf * px, kf * py, 1.0f, 0.0f);
            g_meta[n] = make_float4(m0, m1, m2, kf);
        }
        __syncwarp();
        pv = fmaf(q_sm[wid][ia], q_sm[wid][ib], pv);
        __syncwarp();
    }

#pragma unroll
    for (int i = 0; i < 14; i++) a[i] = wsum(a[i]);
#pragma unroll
    for (int i = 0; i < 20; i++) UQ[i] = wsum(UQ[i]);
    if (lane == 0) {
#pragma unroll
        for (int i = 0; i < 14; i++) red[wid][i] = a[i];
#pragma unroll
        for (int i = 0; i < 20; i++) red[wid][14 + i] = UQ[i];
    }
    if (lane < 20) red[wid][34 + lane] = pv;
    __syncthreads();
    if (threadIdx.x < NSTAT) {
        float s = 0.0f;
#pragma unroll
        for (int w = 0; w < NWARP; w++) s += red[w][threadIdx.x];
        atomicAdd(&g_stats[threadIdx.x], s);
    }
    __threadfence();
    __shared__ unsigned s_last;
    if (threadIdx.x == 0) s_last = atomicAdd(&g_count, 1u);
    __syncthreads();
    if (s_last != GRID1 - 1) return;
    __threadfence();

    // ---------------- finalize (last block only) ----------------
    __shared__ float S[9];
    __shared__ float M[9][9];
    if (threadIdx.x == 0) {
        float st[NSTAT];
#pragma unroll
        for (int i = 0; i < NSTAT; i++) st[i] = __ldcg(&g_stats[i]);

        auto G2 = [&](int i, int j) -> float {
            if (i > j) { int t = i; i = j; j = t; }
            const int base[4] = {0, 4, 7, 9};
            return st[4 + base[i] + (j - i)];
        };
        auto U = [&](int i, int j) -> float { return st[14 + i * 4 + j]; };
        auto V = [&](int i, int j) -> float {
            int lo = i < j ? i : j, hi = i < j ? j : i;
            const int b3[3] = {0, 3, 5};
            return st[34 + b3[lo] + (hi - lo)];
        };
        const float* Qx = st + 26; const float* Qy = st + 30;
        const float* Wx = st + 40; const float* Wy = st + 43; const float* Ksa = st + 46;
        const float Rxx = st[49], Rxy = st[50], Ryy = st[51], Lx = st[52], Ly = st[53];

        S[0] = st[0]; S[1] = st[1]; S[2] = st[2]; S[3] = st[3];
        S[4] = st[0] - Ksa[0]; S[5] = st[1] - Ksa[1]; S[6] = st[2] - Ksa[2];
        S[7] = st[0] - Lx;     S[8] = st[1] - Ly;

        for (int i = 0; i < 4; i++)
            for (int j = 0; j < 4; j++) M[i][j] = G2(i, j);
        for (int j = 0; j < 3; j++)
            for (int i = 0; i < 4; i++) {
                const float m = G2(i, j) - U(j, i);
                M[i][4 + j] = m; M[4 + j][i] = m;
            }
        for (int i = 0; i < 3; i++)
            for (int j = 0; j < 3; j++)
                M[4 + i][4 + j] = G2(i, j) - U(i, j) - U(j, i) + V(i, j);
        for (int i = 0; i < 4; i++) {
            float m = G2(i, 0) - Qx[i]; M[i][7] = m; M[7][i] = m;
            m       = G2(i, 1) - Qy[i]; M[i][8] = m; M[8][i] = m;
        }
        for (int i = 0; i < 3; i++) {
            float m = G2(i, 0) - Qx[i] - U(i, 0) + Wx[i]; M[4 + i][7] = m; M[7][4 + i] = m;
            m       = G2(i, 1) - Qy[i] - U(i, 1) + Wy[i]; M[4 + i][8] = m; M[8][4 + i] = m;
        }
        M[7][7] = G2(0, 0) - 2.0f * Qx[0] + Rxx;
        M[7][8] = G2(0, 1) - Qx[1] - Qy[0] + Rxy; M[8][7] = M[7][8];
        M[8][8] = G2(1, 1) - 2.0f * Qy[1] + Ryy;
    }
    __syncthreads();

    if (threadIdx.x < NSTAT) g_stats[threadIdx.x] = 0.0f;
    if (threadIdx.x == 0)    g_count = 0u;

    const int o = threadIdx.x;
    if (o < 64) {
        float w[9];
#pragma unroll
        for (int j = 0; j < 9; j++) w[j] = Wm[o * 9 + j];
        float mean = 0.0f;
#pragma unroll
        for (int j = 0; j < 9; j++) mean += w[j] * S[j];
        mean *= invNP;
        float e2 = 0.0f;
#pragma unroll
        for (int i = 0; i < 9; i++) {
            float acc = 0.0f;
#pragma unroll
            for (int j = 0; j < 9; j++) acc += w[j] * M[i][j];
            e2 += w[i] * acc;
        }
        e2 *= invNP;
        const float var = e2 - mean * mean;
        const float sc  = gm[o] * rsqrtf(var + 1e-3f);
        const float sh  = bt[o] - mean * sc;

        g_params[0 * 64 + o] = sc * (w[0] + w[4] + w[7]);
        g_params[1 * 64 + o] = sc * (w[1] + w[5] + w[8]);
        g_params[2 * 64 + o] = sc * (w[2] + w[6]);
        g_params[3 * 64 + o] = sc * w[3];
        g_params[4 * 64 + o] = sc * w[4];
        g_params[5 * 64 + o] = sc * w[5];
        g_params[6 * 64 + o] = sc * w[6];
        g_params[7 * 64 + o] = sc * w[7];
        g_params[8 * 64 + o] = sc * w[8];
        g_params[9 * 64 + o] = sh;
    }
}

// ---------------------------------------------------------------------------
// Pass 2: warp/voxel; lane = channels (2l, 2l+1). R4's 2pt f32x2 SoA body;
// A coeffs as 8 packed splats; B/T in smem; NaN tail padding (uniform
// ceil(k/2) loop); off applied post-max; 5 blocks/SM via GRID2 = 148*5.
// ---------------------------------------------------------------------------
__global__ void __launch_bounds__(BLOCK, 5) k_pass2(
    const float4* __restrict__ vox, const int4* __restrict__ coors,
    float2* __restrict__ out, int N)
{
    const int lane = threadIdx.x & 31;
    const int wid  = threadIdx.x >> 5;
    const int warp = blockIdx.x * NWARP + wid;
    const int nwarps = GRID2 * NWARP;
    const int c = lane * 2;

    // B0..B4, T rows staged in smem (register relief)
    __shared__ float sB[6][64];
    for (int i = threadIdx.x; i < 6 * 64; i += BLOCK)
        (&sB[0][0])[i] = g_params[4 * 64 + i];

    // A rows as packed splats (16 regs)
    uint64_t A0pa, A1pa, A2pa, A3pa, A0pb, A1pb, A2pb, A3pb;
    {
        const float2* P = (const float2*)g_params;   // row r, pair: P[r*32 + lane]
        float2 t;
        t = P[0 * 32 + lane]; PACK2(A0pa, t.x, t.x); PACK2(A0pb, t.y, t.y);
        t = P[1 * 32 + lane]; PACK2(A1pa, t.x, t.x); PACK2(A1pb, t.y, t.y);
        t = P[2 * 32 + lane]; PACK2(A2pa, t.x, t.x); PACK2(A2pb, t.y, t.y);
        t = P[3 * 32 + lane]; PACK2(A3pa, t.x, t.x); PACK2(A3pb, t.y, t.y);
    }
    __syncthreads();

    __shared__ __align__(16) float sx[NWARP][32], sy[NWARP][32], sz[NWARP][32], sw[NWARP][32];
    const float NEG_INF = __int_as_float(0xff800000);
    const float QNAN    = __int_as_float(0x7fffffff);

    for (int n = warp; n < N; n += nwarps) {
        const float4 meta = g_meta[n];
        const int k = (int)meta.w;
        if (k == 0) {
            out[(size_t)n * 32 + lane] = make_float2(0.0f, 0.0f);
            continue;
        }
        float4 u = vox[(size_t)n * 32 + lane];
        if (lane >= k) { u.x = QNAN; u.y = QNAN; u.z = QNAN; u.w = QNAN; }
        sx[wid][lane] = u.x; sy[wid][lane] = u.y; sz[wid][lane] = u.z; sw[wid][lane] = u.w;

        const int4 cc = coors[n];
        const float px = (float)cc.y * 0.1f + (0.05f - 20.0f);
        const float py = (float)cc.z * 0.1f + (0.05f - 20.0f);

        // off = T - B.(m, px, py) from smem coefficients
        float ta = sB[0][c] * meta.x;
        ta = fmaf(sB[1][c], meta.y, ta); ta = fmaf(sB[2][c], meta.z, ta);
        ta = fmaf(sB[3][c], px, ta);     ta = fmaf(sB[4][c], py, ta);
        const float offa = sB[5][c] - ta;
        float tb = sB[0][c + 1] * meta.x;
        tb = fmaf(sB[1][c + 1], meta.y, tb); tb = fmaf(sB[2][c + 1], meta.z, tb);
        tb = fmaf(sB[3][c + 1], px, tb);     tb = fmaf(sB[4][c + 1], py, tb);
        const float offb = sB[5][c + 1] - tb;

        __syncwarp();
        const uint64_t* X = (const uint64_t*)sx[wid];
        const uint64_t* Y = (const uint64_t*)sy[wid];
        const uint64_t* Z = (const uint64_t*)sz[wid];
        const uint64_t* W = (const uint64_t*)sw[wid];

        float ra0 = NEG_INF, ra1 = NEG_INF, rb0 = NEG_INF, rb1 = NEG_INF;
        const int k2 = (k + 1) >> 1;          // NaN padding makes this uniform
#pragma unroll 4
        for (int j = 0; j < k2; j++) {
            const uint64_t x2 = X[j], y2 = Y[j], z2 = Z[j], w2 = W[j];
            uint64_t t;
            float lo, hi;
            MUL2(t, w2, A3pa); FMA2(t, z2, A2pa, t); FMA2(t, y2, A1pa, t); FMA2(t, x2, A0pa, t);
            UNPACK2(lo, hi, t);
            ra0 = fmaxf(ra0, lo); ra1 = fmaxf(ra1, hi);
            MUL2(t, w2, A3pb); FMA2(t, z2, A2pb, t); FMA2(t, y2, A1pb, t); FMA2(t, x2, A0pb, t);
            UNPACK2(lo, hi, t);
            rb0 = fmaxf(rb0, lo); rb1 = fmaxf(rb1, hi);
        }
        const float ra = fmaxf(fmaxf(ra0, ra1) + offa, 0.0f);
        const float rb = fmaxf(fmaxf(rb0, rb1) + offb, 0.0f);
        out[(size_t)n * 32 + lane] = make_float2(ra, rb);
        __syncwarp();
    }
}

// ---------------------------------------------------------------------------
extern "C" void kernel_launch(void* const* d_in, const int* in_sizes, int n_in,
                              void* d_out, int out_size)
{
    const float* voxels = (const float*)d_in[0];
    const int*   npts   = (const int*)d_in[1];
    const int*   coors  = (const int*)d_in[2];
    const float* W      = (const float*)d_in[3];
    const float* gamma  = (const float*)d_in[4];
    const float* beta   = (const float*)d_in[5];
    float*       out    = (float*)d_out;
    const int N = in_sizes[1];

    k_pass1<<<GRID1, BLOCK>>>((const float4*)voxels, npts, (const int4*)coors,
                              W, gamma, beta, 1.0f / ((float)N * 32.0f), N);
    k_pass2<<<GRID2, BLOCK>>>((const float4*)voxels, (const int4*)coors,
                              (float2*)out, N);
}